// round 13
// baseline (speedup 1.0000x reference)
#include <cuda_runtime.h>

#define Bz 32
#define Sz 256
#define Iz 512
#define Hz 256                /* query dim — H=256 (NOT 80; M=80 is the frame dim) */
#define Mz 80
#define Cz 1024
#define C2z 512
#define LOCz 32
#define Kz 31
#define Tz 800
#define XWz (Hz + Iz)         /* 768  */
#define TINz (Iz + Mz + Cz)   /* 1616 */
#define GRID 128
#define NTHR 256

// ---------------- persistent device scratch ----------------
__device__ __align__(16) float g_key[Bz][Sz][C2z];   // enc @ w_k^T + b_k
__device__ __align__(16) float g_hT[2][Cz][Bz];      // h transposed [j][b] (GEMV reads)
__device__ __align__(16) float g_hB[2][Bz][Cz];      // h batch-major (prologue reads)
__device__ __align__(16) float g_prevT[Iz][Bz];      // attend/prev transposed
__device__ __align__(16) float g_alpha[Bz][Sz];
__device__ __align__(16) float g_align_s[Bz][Sz];
__device__ __align__(16) float g_gsum[Bz][2 * Cz];   // r,z gate raw sums (biased)
__device__ __align__(16) float g_gxn[Bz][Cz];        // n-gate x-part (biased)
__device__ __align__(16) float g_ghn[Bz][Cz];        // n-gate h-part (biased)
__device__ __align__(16) float g_wcomb[C2z][Kz];     // fused location conv
__device__ __align__(16) float g_ep[4][Bz][Sz];      // energy partials per c-slab
__device__ __align__(16) float g_zpart[32][Bz];      // trans-gate partials per unit
__device__ unsigned g_cnt;
__device__ volatile unsigned g_epoch;

// ---------------- helpers ----------------
__device__ __forceinline__ float fsig(float x) {
    return __fdividef(1.f, 1.f + __expf(-x));
}
__device__ __forceinline__ float ftanh(float x) {
    float ax = fabsf(x);
    float e  = __expf(-2.f * ax);
    float r  = __fdividef(1.f - e, 1.f + e);
    return copysignf(r, x);
}
__device__ __forceinline__ float dot4(float4 a, float4 b) {
    return a.x * b.x + a.y * b.y + a.z * b.z + a.w * b.w;
}
__device__ __forceinline__ float4 f4fma(float s, float4 v, float4 a) {
    a.x = fmaf(s, v.x, a.x);
    a.y = fmaf(s, v.y, a.y);
    a.z = fmaf(s, v.z, a.z);
    a.w = fmaf(s, v.w, a.w);
    return a;
}

// epoch-based grid barrier; every thread fences on both sides (release+acquire)
__device__ __forceinline__ void gsync(unsigned& e) {
    __threadfence();
    __syncthreads();
    if (threadIdx.x == 0) {
        if (atomicAdd(&g_cnt, 1u) == GRID - 1) {
            g_cnt = 0;
            __threadfence();
            g_epoch = e + 1;
        } else {
            while (g_epoch == e) { }
        }
    }
    __syncthreads();
    __threadfence();
    e++;
}

// ---------------- the persistent kernel ----------------
__global__ void __launch_bounds__(NTHR, 1)
aligner_persistent(const float* __restrict__ enc,
                   const float* __restrict__ queries,
                   const float* __restrict__ outputs,
                   const float* __restrict__ mask,
                   const float* __restrict__ w_ih,
                   const float* __restrict__ w_hh,
                   const float* __restrict__ b_ih,
                   const float* __restrict__ b_hh,
                   const float* __restrict__ w_q,
                   const float* __restrict__ w_loc1,
                   const float* __restrict__ w_loc2,
                   const float* __restrict__ w_k,
                   const float* __restrict__ b_k,
                   const float* __restrict__ w_agg,
                   const float* __restrict__ w_t1,
                   const float* __restrict__ b_t1,
                   const float* __restrict__ w_t2,
                   float* __restrict__ out) {
    __shared__ __align__(16) float sm[8448];  // 33 KB, phase-aliased
    const int cta = blockIdx.x;
    const int tid = threadIdx.x;
    unsigned ep = g_epoch;  // stable before any barrier

    // ================= phase 0: init + wcomb + key =================
    {
        int c0 = cta * 4;
        for (int idx = tid; idx < 4 * Kz; idx += NTHR) {
            int c = c0 + idx / Kz, k = idx % Kz;
            float a = 0.f;
            for (int l = 0; l < LOCz; l++)
                a += w_loc2[c * LOCz + l] * w_loc1[l * Kz + k];
            g_wcomb[c][k] = a;
        }
        for (int idx = cta * NTHR + tid; idx < Cz * Bz; idx += GRID * NTHR) {
            ((float*)g_hT)[idx] = 0.f;
            ((float*)g_hB)[idx] = 0.f;
        }
        for (int idx = cta * NTHR + tid; idx < Bz * Sz; idx += GRID * NTHR) {
            int b = idx / Sz, s = idx % Sz;
            g_alpha[b][s]   = (s == 0) ? 1.f : 0.f;
            g_align_s[b][s] = 1.f / (float)Sz;
        }
        for (int idx = cta * NTHR + tid; idx < Iz * Bz; idx += GRID * NTHR) {
            int i = idx / Bz, b = idx % Bz;
            g_prevT[i][b] = enc[((size_t)b * Sz) * Iz + i];  // alpha0 one-hot @ s=0
        }
        for (int idx = cta * NTHR + tid; idx < 32 * Bz; idx += GRID * NTHR)
            ((float*)g_zpart)[idx] = 0.f;  // sigmoid(0)=0.5 = trans0

        // key projection: CTA = (b, s-quarter)
        int b = cta >> 2, sq = cta & 3;
        float* esm = sm;  // 16 x 512
        for (int tile = 0; tile < 4; tile++) {
            int s0 = sq * 64 + tile * 16;
            __syncthreads();
            const float* epp = enc + ((size_t)b * Sz + s0) * Iz;
            for (int i = tid; i < 16 * Iz; i += NTHR) esm[i] = epp[i];
            __syncthreads();
            for (int ch = 0; ch < 2; ch++) {
                int c = ch * 256 + tid;
                const float4* wr = (const float4*)(w_k + (size_t)c * Iz);
                const float4* ef = (const float4*)esm;
                float acc[16];
#pragma unroll
                for (int s = 0; s < 16; s++) acc[s] = 0.f;
                for (int k4 = 0; k4 < Iz / 4; k4++) {
                    float4 w = wr[k4];
#pragma unroll
                    for (int s = 0; s < 16; s++)
                        acc[s] += dot4(w, ef[s * (Iz / 4) + k4]);
                }
                float bk = b_k[c];
#pragma unroll
                for (int s = 0; s < 16; s++) g_key[b][s0 + s][c] = acc[s] + bk;
            }
        }
    }
    gsync(ep);

    // ================= time loop =================
    for (int t = 0; t < Tz; t++) {
        const int cur = t & 1, nxt = cur ^ 1;

        // ---------- P1: GRU dot-sums (ctas 0..95) || TRANS(t-1) (ctas 96..127) ----------
        if (cta < 96) {
            float* qsm = sm;  // [Hz][Bz] query transposed: 256*32 = 8192 floats
            for (int idx = tid; idx < Hz * Bz; idx += NTHR) {
                int b = idx / Hz, k = idx % Hz;
                qsm[k * Bz + b] = queries[((size_t)b * Tz + t) * Hz + k];
            }
            __syncthreads();
            int rl = tid >> 3, bq = tid & 7;
            int r = cta * 32 + rl;  // global gate-row in [0, 3072)
            const float4* wx = (const float4*)(w_ih + (size_t)r * XWz);
            const float4* wh = (const float4*)(w_hh + (size_t)r * Cz);
            float4 ax = make_float4(0.f, 0.f, 0.f, 0.f);
            float4 ah = make_float4(0.f, 0.f, 0.f, 0.f);
#pragma unroll 2
            for (int k4 = 0; k4 < Hz / 4; k4++) {  // query part (smem)
                float4 w = wx[k4];
                int kb = k4 * 4 * Bz + bq * 4;
                ax = f4fma(w.x, *(const float4*)&qsm[kb], ax);
                ax = f4fma(w.y, *(const float4*)&qsm[kb + Bz], ax);
                ax = f4fma(w.z, *(const float4*)&qsm[kb + 2 * Bz], ax);
                ax = f4fma(w.w, *(const float4*)&qsm[kb + 3 * Bz], ax);
            }
            const float4* pv = (const float4*)g_prevT;
#pragma unroll 2
            for (int k4 = 0; k4 < Iz / 4; k4++) {  // prev part
                float4 w = wx[Hz / 4 + k4];
                int kb = k4 * 32 + bq;
                ax = f4fma(w.x, pv[kb], ax);
                ax = f4fma(w.y, pv[kb + 8], ax);
                ax = f4fma(w.z, pv[kb + 16], ax);
                ax = f4fma(w.w, pv[kb + 24], ax);
            }
            const float4* hv4 = (const float4*)g_hT[cur];
#pragma unroll 2
            for (int k4 = 0; k4 < Cz / 4; k4++) {  // hidden part
                float4 w = wh[k4];
                int kb = k4 * 32 + bq;
                ah = f4fma(w.x, hv4[kb], ah);
                ah = f4fma(w.y, hv4[kb + 8], ah);
                ah = f4fma(w.z, hv4[kb + 16], ah);
                ah = f4fma(w.w, hv4[kb + 24], ah);
            }
            int b0 = bq * 4;
            if (cta < 64) {  // r- and z-gates: combined biased sum
                float bb = b_ih[r] + b_hh[r];
                g_gsum[b0 + 0][r] = ax.x + ah.x + bb;
                g_gsum[b0 + 1][r] = ax.y + ah.y + bb;
                g_gsum[b0 + 2][r] = ax.z + ah.z + bb;
                g_gsum[b0 + 3][r] = ax.w + ah.w + bb;
            } else {  // n-gate: keep x/h parts separate
                int j = r - 2048;
                float bx = b_ih[r], bh = b_hh[r];
                g_gxn[b0 + 0][j] = ax.x + bx;
                g_gxn[b0 + 1][j] = ax.y + bx;
                g_gxn[b0 + 2][j] = ax.z + bx;
                g_gxn[b0 + 3][j] = ax.w + bx;
                g_ghn[b0 + 0][j] = ah.x + bh;
                g_ghn[b0 + 1][j] = ah.y + bh;
                g_ghn[b0 + 2][j] = ah.z + bh;
                g_ghn[b0 + 3][j] = ah.w + bh;
            }
        } else if (t > 0) {  // TRANS(t-1)
            int tt = t - 1;
            float* fsm = sm;              // [Mz][Bz] frame transposed
            float* part = sm + Mz * Bz;   // [32][32]
            for (int idx = tid; idx < Mz * Bz; idx += NTHR) {
                int b = idx / Mz, k = idx % Mz;
                fsm[k * Bz + b] = outputs[((size_t)b * Tz + tt) * Mz + k];
            }
            __syncthreads();
            int rl = tid >> 3, bq = tid & 7;
            int unit = cta - 96;
            int r = unit * 32 + rl;  // row in [0, 1024)
            const float4* wt = (const float4*)(w_t1 + (size_t)r * TINz);
            float4 acc = make_float4(0.f, 0.f, 0.f, 0.f);
            const float4* pv = (const float4*)g_prevT;
#pragma unroll 2
            for (int k4 = 0; k4 < Iz / 4; k4++) {  // attend part
                float4 w = wt[k4];
                int kb = k4 * 32 + bq;
                acc = f4fma(w.x, pv[kb], acc);
                acc = f4fma(w.y, pv[kb + 8], acc);
                acc = f4fma(w.z, pv[kb + 16], acc);
                acc = f4fma(w.w, pv[kb + 24], acc);
            }
#pragma unroll 2
            for (int k4 = 0; k4 < Mz / 4; k4++) {  // frame part
                float4 w = wt[Iz / 4 + k4];
                int kb = k4 * 4 * Bz + bq * 4;
                acc = f4fma(w.x, *(const float4*)&fsm[kb], acc);
                acc = f4fma(w.y, *(const float4*)&fsm[kb + Bz], acc);
                acc = f4fma(w.z, *(const float4*)&fsm[kb + 2 * Bz], acc);
                acc = f4fma(w.w, *(const float4*)&fsm[kb + 3 * Bz], acc);
            }
            const float4* hv4 = (const float4*)g_hT[cur];  // h_new(t-1)
#pragma unroll 2
            for (int k4 = 0; k4 < Cz / 4; k4++) {
                float4 w = wt[(Iz + Mz) / 4 + k4];
                int kb = k4 * 32 + bq;
                acc = f4fma(w.x, hv4[kb], acc);
                acc = f4fma(w.y, hv4[kb + 8], acc);
                acc = f4fma(w.z, hv4[kb + 16], acc);
                acc = f4fma(w.w, hv4[kb + 24], acc);
            }
            float bt = b_t1[r], w2 = w_t2[r];
            int b0 = bq * 4;
            part[rl * 32 + b0 + 0] = ftanh(acc.x + bt) * w2;
            part[rl * 32 + b0 + 1] = ftanh(acc.y + bt) * w2;
            part[rl * 32 + b0 + 2] = ftanh(acc.z + bt) * w2;
            part[rl * 32 + b0 + 3] = ftanh(acc.w + bt) * w2;
            __syncthreads();
            if (tid < 32) {
                float s = 0.f;
#pragma unroll
                for (int r2 = 0; r2 < 32; r2++) s += part[r2 * 32 + tid];
                g_zpart[unit][tid] = s;
            }
        }
        gsync(ep);

        // ---------- P2: GRU finish + q-proj + location conv + energy ----------
        {
            int b = cta >> 2, cs = cta & 3;
            float* hsm  = sm;          // 1024
            float* apad = sm + 1024;   // 291
            float* qp   = sm + 1316;   // 256
            float* q_sm = sm + 1572;   // 128
            float* epw  = sm + 1700;   // 1024

            {   // h_new = (1-z)*n + z*h  (all 4 slab-CTAs compute redundantly)
                int j = tid * 4;
                float4 sr  = *(const float4*)&g_gsum[b][j];
                float4 szv = *(const float4*)&g_gsum[b][Cz + j];
                float4 xn  = *(const float4*)&g_gxn[b][j];
                float4 hn  = *(const float4*)&g_ghn[b][j];
                float4 ho  = *(const float4*)&g_hB[cur][b][j];
                float4 hv;
                {
                    float rg = fsig(sr.x), zg = fsig(szv.x);
                    hv.x = (1.f - zg) * ftanh(xn.x + rg * hn.x) + zg * ho.x;
                }
                {
                    float rg = fsig(sr.y), zg = fsig(szv.y);
                    hv.y = (1.f - zg) * ftanh(xn.y + rg * hn.y) + zg * ho.y;
                }
                {
                    float rg = fsig(sr.z), zg = fsig(szv.z);
                    hv.z = (1.f - zg) * ftanh(xn.z + rg * hn.z) + zg * ho.z;
                }
                {
                    float rg = fsig(sr.w), zg = fsig(szv.w);
                    hv.w = (1.f - zg) * ftanh(xn.w + rg * hn.w) + zg * ho.w;
                }
                *(float4*)&hsm[j] = hv;
                if (cs == 0) *(float4*)&g_hB[nxt][b][j] = hv;
            }
            for (int i = tid; i < Sz + 35; i += NTHR) {
                int s = i - 15;
                apad[i] = (s >= 0 && s < Sz) ? g_align_s[b][s] : 0.f;
            }
            __syncthreads();
            {   // transposed h_new write, j-range partitioned by slab
                int j = cs * 256 + tid;
                g_hT[nxt][j][b] = hsm[j];
            }
            {   // q[c] = w_q[c,:] . h_new   (2 threads per c)
                int cl = tid >> 1, half = tid & 1;
                int c = cs * 128 + cl;
                const float4* wq = (const float4*)(w_q + (size_t)c * Cz + half * 512);
                const float4* hv = (const float4*)(hsm + half * 512);
                float a = 0.f;
#pragma unroll 4
                for (int k = 0; k < 128; k++) a += dot4(wq[k], hv[k]);
                qp[tid] = a;
            }
            __syncthreads();
            if (tid < 128) q_sm[tid] = qp[2 * tid] + qp[2 * tid + 1];
            __syncthreads();

            int w = tid >> 5, lane = tid & 31;
            int cg = w & 3, sh = w >> 2;
            int cl = cg * 32 + lane;
            int c = cs * 128 + cl;
            float wc[Kz];
#pragma unroll
            for (int k = 0; k < Kz; k++) wc[k] = g_wcomb[c][k];
            float wa = w_agg[c];
            float qc = q_sm[cl];
            int s0 = sh * 128;
            for (int sb = 0; sb < 32; sb++) {
                int s = s0 + sb * 4;
                float a0 = qc + g_key[b][s][c];
                float a1 = qc + g_key[b][s + 1][c];
                float a2 = qc + g_key[b][s + 2][c];
                float a3 = qc + g_key[b][s + 3][c];
                float x0 = apad[s], x1 = apad[s + 1], x2 = apad[s + 2], x3 = apad[s + 3];
#pragma unroll
                for (int k = 0; k < Kz; k++) {
                    float wk = wc[k];
                    a0 = fmaf(wk, x0, a0);
                    a1 = fmaf(wk, x1, a1);
                    a2 = fmaf(wk, x2, a2);
                    a3 = fmaf(wk, x3, a3);
                    x0 = x1; x1 = x2; x2 = x3; x3 = apad[s + k + 4];
                }
                float e0 = ftanh(a0) * wa;
                float e1 = ftanh(a1) * wa;
                float e2 = ftanh(a2) * wa;
                float e3 = ftanh(a3) * wa;
#pragma unroll
                for (int off = 16; off; off >>= 1) {
                    e0 += __shfl_xor_sync(0xffffffffu, e0, off);
                    e1 += __shfl_xor_sync(0xffffffffu, e1, off);
                    e2 += __shfl_xor_sync(0xffffffffu, e2, off);
                    e3 += __shfl_xor_sync(0xffffffffu, e3, off);
                }
                if (lane == 0) {  // unique (cg, s) writer — deterministic
                    epw[cg * 256 + s]     = e0;
                    epw[cg * 256 + s + 1] = e1;
                    epw[cg * 256 + s + 2] = e2;
                    epw[cg * 256 + s + 3] = e3;
                }
            }
            __syncthreads();
            g_ep[cs][b][tid] = epw[tid] + epw[256 + tid] + epw[512 + tid] + epw[768 + tid];
        }
        gsync(ep);

        // ---------- P3: softmax + alpha update + attend (ctas 0..31) ----------
        if (cta < Bz) {
            int b = cta, s = tid;
            float* red   = sm;         // 256
            float* alnew = sm + 256;   // 256
            float* aold  = sm + 512;   // 257
            float* attb  = sm + 784;   // 512 (float4 x 128)
            float* trsp  = sm + 1300;  // 1

            if (tid < 32) {  // trans = sigmoid(sum of 32 deterministic partials)
                float zp = g_zpart[tid][b];
#pragma unroll
                for (int off = 16; off; off >>= 1)
                    zp += __shfl_xor_sync(0xffffffffu, zp, off);
                if (tid == 0) trsp[0] = fsig(zp);
            }
            aold[tid + 1] = g_alpha[b][tid];
            if (tid == 0) aold[0] = 0.f;

            float e = g_ep[0][b][s] + g_ep[1][b][s] + g_ep[2][b][s] + g_ep[3][b][s];
            if (mask[b * Sz + s] == 0.f) e = -1e30f;

            red[tid] = e; __syncthreads();
            for (int o = 128; o; o >>= 1) {
                if (tid < o) red[tid] = fmaxf(red[tid], red[tid + o]);
                __syncthreads();
            }
            float m = red[0]; __syncthreads();
            float ex = __expf(e - m);
            red[tid] = ex; __syncthreads();
            for (int o = 128; o; o >>= 1) {
                if (tid < o) red[tid] += red[tid + o];
                __syncthreads();
            }
            float aln = __fdividef(ex, red[0]);
            float tr = trsp[0];
            float raw = ((1.f - tr) * aold[s + 1] + tr * aold[s] + 1e-7f) * aln;
            __syncthreads();
            red[tid] = raw; __syncthreads();
            for (int o = 128; o; o >>= 1) {
                if (tid < o) red[tid] += red[tid + o];
                __syncthreads();
            }
            float an = __fdividef(raw, red[0]);

            g_alpha[b][s]   = an;
            g_align_s[b][s] = aln;
            out[((size_t)b * Tz + t) * Sz + s] = an;
            alnew[s] = an;
            __syncthreads();

            // attend = enc^T alpha_new  -> g_prevT (prev for step t+1)
            int i4 = tid & 127, shh = tid >> 7;
            const float4* eb = (const float4*)(enc + (size_t)b * Sz * Iz);
            float4 acc = make_float4(0.f, 0.f, 0.f, 0.f);
            for (int s2 = shh * 128; s2 < shh * 128 + 128; s2++) {
                float a = alnew[s2];
                float4 ev = eb[(size_t)s2 * (Iz / 4) + i4];
                acc.x = fmaf(a, ev.x, acc.x);
                acc.y = fmaf(a, ev.y, acc.y);
                acc.z = fmaf(a, ev.z, acc.z);
                acc.w = fmaf(a, ev.w, acc.w);
            }
            if (shh == 0) *(float4*)&attb[i4 * 4] = acc;
            __syncthreads();
            if (shh == 1) {
                float4 o = *(const float4*)&attb[i4 * 4];
                int i = i4 * 4;
                g_prevT[i][b]     = o.x + acc.x;
                g_prevT[i + 1][b] = o.y + acc.y;
                g_prevT[i + 2][b] = o.z + acc.z;
                g_prevT[i + 3][b] = o.w + acc.w;
            }
        }
        gsync(ep);
    }
}

// ---------------- driver: ONE graph node ----------------
extern "C" void kernel_launch(void* const* d_in, const int* in_sizes, int n_in,
                              void* d_out, int out_size) {
    (void)in_sizes; (void)n_in; (void)out_size;
    const float* enc     = (const float*)d_in[0];
    const float* queries = (const float*)d_in[1];
    const float* outputs = (const float*)d_in[2];
    const float* mask    = (const float*)d_in[3];
    const float* w_ih    = (const float*)d_in[4];
    const float* w_hh    = (const float*)d_in[5];
    const float* b_ih    = (const float*)d_in[6];
    const float* b_hh    = (const float*)d_in[7];
    const float* w_q     = (const float*)d_in[8];
    const float* w_loc1  = (const float*)d_in[9];
    const float* w_loc2  = (const float*)d_in[10];
    const float* w_k     = (const float*)d_in[11];
    const float* b_k     = (const float*)d_in[12];
    const float* w_agg   = (const float*)d_in[13];
    const float* w_t1    = (const float*)d_in[14];
    const float* b_t1    = (const float*)d_in[15];
    const float* w_t2    = (const float*)d_in[16];
    float* out = (float*)d_out;

    aligner_persistent<<<GRID, NTHR>>>(enc, queries, outputs, mask,
                                       w_ih, w_hh, b_ih, b_hh, w_q,
                                       w_loc1, w_loc2, w_k, b_k, w_agg,
                                       w_t1, b_t1, w_t2, out);
}